// round 5
// baseline (speedup 1.0000x reference)
#include <cuda_runtime.h>
#include <cuda_bf16.h>
#include <stdint.h>

// alpha[e] = 1 / in_degree(dst[e]) per relation: the reference's per-dst edge
// softmax is over identical logits (e - emax == 0 exactly -> ex == 1 ->
// denom == count), so all GEMM/elu/attn work is dead w.r.t. the output.
//
// Pipeline (3 kernels, no memset):
//   hist  : 8 edges/thread, 2x int4 loads, 8 REDG atomics into g_deg
//   recip : per NODE 1/deg -> g_rdeg, then RESETS g_deg to 0 (self-restoring
//           across graph replays; __device__ globals start zeroed at load)
//   alpha : 8 edges/thread gather from L2-resident g_rdeg, float4 stcg out

#define MAXN 131072          // >= N (100000), padded

__device__ int   g_deg[2 * MAXN];    // zero-initialized at module load
__device__ float g_rdeg[2 * MAXN];

__global__ void hist_kernel(const int4* __restrict__ dst_ui,
                            const int4* __restrict__ dst_iu,
                            int nthr)   // nthr = E/8 per relation
{
    int i = blockIdx.x * blockDim.x + threadIdx.x;
    const int4* src;
    int base;
    if (i < nthr)          { src = dst_ui; base = 0; }
    else if (i < 2 * nthr) { src = dst_iu; base = MAXN; i -= nthr; }
    else return;

    int4 a = __ldg(&src[2 * i]);
    int4 b = __ldg(&src[2 * i + 1]);
    atomicAdd(&g_deg[base + a.x], 1);
    atomicAdd(&g_deg[base + a.y], 1);
    atomicAdd(&g_deg[base + a.z], 1);
    atomicAdd(&g_deg[base + a.w], 1);
    atomicAdd(&g_deg[base + b.x], 1);
    atomicAdd(&g_deg[base + b.y], 1);
    atomicAdd(&g_deg[base + b.z], 1);
    atomicAdd(&g_deg[base + b.w], 1);
}

__global__ void recip_kernel()
{
    int i = blockIdx.x * blockDim.x + threadIdx.x;
    if (i < 2 * MAXN) {
        int d = g_deg[i];
        // exact div.rn matches reference; deg==0 -> inf, never read back
        g_rdeg[i] = 1.0f / (float)d;
        g_deg[i] = 0;          // restore invariant for the next replay
    }
}

__global__ void alpha_kernel(const int4* __restrict__ dst_ui,
                             const int4* __restrict__ dst_iu,
                             float4* __restrict__ out,   // [0,E) ui then [E,2E) iu
                             int nthr, int nvec)          // nthr=E/8, nvec=E/4
{
    int i = blockIdx.x * blockDim.x + threadIdx.x;
    const int4* src;
    int base, obase;
    if (i < nthr)          { src = dst_ui; base = 0;    obase = 0; }
    else if (i < 2 * nthr) { src = dst_iu; base = MAXN; obase = nvec; i -= nthr; }
    else return;

    int4 a = __ldg(&src[2 * i]);
    int4 b = __ldg(&src[2 * i + 1]);
    float4 r0, r1;
    r0.x = g_rdeg[base + a.x];
    r0.y = g_rdeg[base + a.y];
    r0.z = g_rdeg[base + a.z];
    r0.w = g_rdeg[base + a.w];
    r1.x = g_rdeg[base + b.x];
    r1.y = g_rdeg[base + b.y];
    r1.z = g_rdeg[base + b.z];
    r1.w = g_rdeg[base + b.w];
    __stcg(&out[obase + 2 * i],     r0);
    __stcg(&out[obase + 2 * i + 1], r1);
}

// ragged tail (E % 8 != 0): never fires for E = 1e6, kept for generality
__global__ void tail_full_kernel(const int* __restrict__ dst_ui,
                                 const int* __restrict__ dst_iu,
                                 float* __restrict__ out,
                                 int start, int E)
{
    int i = start + blockIdx.x * blockDim.x + threadIdx.x;
    if (i < E) {
        out[i]     = g_rdeg[dst_ui[i]];
        out[E + i] = g_rdeg[MAXN + dst_iu[i]];
    }
}

extern "C" void kernel_launch(void* const* d_in, const int* in_sizes, int n_in,
                              void* d_out, int out_size)
{
    const int* dst_ui = (const int*)d_in[12];
    const int* dst_iu = (const int*)d_in[14];
    float* out = (float*)d_out;

    const int E = in_sizes[12];       // 1,000,000
    const int nthr = E / 8;
    const int nvec = E / 4;
    const int TB = 512;

    hist_kernel<<<(2 * nthr + TB - 1) / TB, TB>>>(
        (const int4*)dst_ui, (const int4*)dst_iu, nthr);

    recip_kernel<<<(2 * MAXN + TB - 1) / TB, TB>>>();

    alpha_kernel<<<(2 * nthr + TB - 1) / TB, TB>>>(
        (const int4*)dst_ui, (const int4*)dst_iu, (float4*)out, nthr, nvec);

    if (E % 8 != 0) {
        int start = (E / 8) * 8;
        int rem = E - start;
        tail_full_kernel<<<(rem + TB - 1) / TB, TB>>>(dst_ui, dst_iu, out, start, E);
    }
}

// round 6
// speedup vs baseline: 1.0654x; 1.0654x over previous
#include <cuda_runtime.h>
#include <cuda_bf16.h>
#include <stdint.h>

// alpha[e] = 1 / in_degree(dst[e]) per relation: the reference's per-dst edge
// softmax is over identical logits (e - emax == 0 exactly -> ex == 1 ->
// denom == count), so all GEMM/elu/attn work is dead w.r.t. the output.
//
// Pipeline (3 kernels, persistent grid-stride, no memset):
//   hist  : int4 loads, 4 REDG atomics/iter, full-wave persistent grid
//   recip : per NODE 1/deg -> g_rdeg, resets g_deg to 0 (self-restoring
//           across graph replays; __device__ globals start zeroed at load)
//   alpha : int4 load + 4 L2-resident gathers + float4 stcg store, persistent

#define MAXN 131072          // >= N (100000), padded

__device__ int   g_deg[2 * MAXN];    // zero-initialized at module load
__device__ float g_rdeg[2 * MAXN];

// Persistent: grid sized to one full wave; every SM stays at max warps for the
// whole kernel. 4 edges per loop iteration via one coalesced int4 load.
__global__ void hist_kernel(const int4* __restrict__ dst_ui,
                            const int4* __restrict__ dst_iu,
                            int nvec)   // nvec = E/4 per relation
{
    int stride = gridDim.x * blockDim.x;
    for (int v = blockIdx.x * blockDim.x + threadIdx.x; v < 2 * nvec; v += stride) {
        int4 x;
        int base;
        if (v < nvec) { x = __ldg(&dst_ui[v]);        base = 0;    }
        else          { x = __ldg(&dst_iu[v - nvec]); base = MAXN; }
        atomicAdd(&g_deg[base + x.x], 1);
        atomicAdd(&g_deg[base + x.y], 1);
        atomicAdd(&g_deg[base + x.z], 1);
        atomicAdd(&g_deg[base + x.w], 1);
    }
}

__global__ void recip_kernel()
{
    int i4 = blockIdx.x * blockDim.x + threadIdx.x;   // one int4 per thread
    if (i4 < (2 * MAXN) / 4) {
        int4* dp = reinterpret_cast<int4*>(g_deg) + i4;
        int4 d = *dp;
        float4 r;
        // exact div.rn matches reference; deg==0 -> inf, never read back
        r.x = 1.0f / (float)d.x;
        r.y = 1.0f / (float)d.y;
        r.z = 1.0f / (float)d.z;
        r.w = 1.0f / (float)d.w;
        reinterpret_cast<float4*>(g_rdeg)[i4] = r;
        *dp = make_int4(0, 0, 0, 0);   // restore invariant for the next replay
    }
}

__global__ void alpha_kernel(const int4* __restrict__ dst_ui,
                             const int4* __restrict__ dst_iu,
                             float4* __restrict__ out,   // [0,nvec) ui, [nvec,2nvec) iu
                             int nvec)
{
    int stride = gridDim.x * blockDim.x;
    for (int v = blockIdx.x * blockDim.x + threadIdx.x; v < 2 * nvec; v += stride) {
        int4 x;
        int base;
        if (v < nvec) { x = __ldg(&dst_ui[v]);        base = 0;    }
        else          { x = __ldg(&dst_iu[v - nvec]); base = MAXN; }
        float4 r;
        r.x = g_rdeg[base + x.x];
        r.y = g_rdeg[base + x.y];
        r.z = g_rdeg[base + x.z];
        r.w = g_rdeg[base + x.w];
        __stcg(&out[v], r);
    }
}

// ragged tail (E % 4 != 0): never fires for E = 1e6, kept for generality
__global__ void tail_full_kernel(const int* __restrict__ dst_ui,
                                 const int* __restrict__ dst_iu,
                                 float* __restrict__ out,
                                 int start, int E)
{
    int i = start + blockIdx.x * blockDim.x + threadIdx.x;
    if (i < E) {
        out[i]     = g_rdeg[dst_ui[i]];
        out[E + i] = g_rdeg[MAXN + dst_iu[i]];
    }
}

extern "C" void kernel_launch(void* const* d_in, const int* in_sizes, int n_in,
                              void* d_out, int out_size)
{
    const int* dst_ui = (const int*)d_in[12];
    const int* dst_iu = (const int*)d_in[14];
    float* out = (float*)d_out;

    const int E = in_sizes[12];       // 1,000,000
    const int nvec = E / 4;
    const int TB = 256;

    // One full wave: 148 SMs x 8 CTAs x 256 thr = 64 warps/SM (max occupancy).
    const int GRID_PERSIST = 148 * 8;

    hist_kernel<<<GRID_PERSIST, TB>>>(
        (const int4*)dst_ui, (const int4*)dst_iu, nvec);

    recip_kernel<<<((2 * MAXN) / 4 + TB - 1) / TB, TB>>>();

    alpha_kernel<<<GRID_PERSIST, TB>>>(
        (const int4*)dst_ui, (const int4*)dst_iu, (float4*)out, nvec);

    if (E % 4 != 0) {
        int start = (E / 4) * 4;
        int rem = E - start;
        tail_full_kernel<<<(rem + TB - 1) / TB, TB>>>(dst_ui, dst_iu, out, start, E);
    }
}

// round 7
// speedup vs baseline: 1.0713x; 1.0056x over previous
#include <cuda_runtime.h>
#include <cuda_bf16.h>
#include <stdint.h>

// alpha[e] = 1 / in_degree(dst[e]) per relation: the reference's per-dst edge
// softmax is over identical logits (e - emax == 0 exactly -> ex == 1 ->
// denom == count), so all GEMM/elu/attn work is dead w.r.t. the output.
//
// The two relations (ui, iu) are fully independent pipelines. Capture forks
// them onto two streams so relation B's atomic-bound histogram overlaps
// relation A's DRAM-bound recip/alpha (complementary resources).
//
//   hist  : persistent, int4 loads, 4 REDG atomics/iter  (L2-atomic bound)
//   recip : per node 1/deg -> g_rdeg, resets g_deg to 0  (self-restoring
//           across replays; __device__ globals start zeroed at load)
//   alpha : int4 load + 4 L2 gathers + float4 stcg store (DRAM bound)

#define MAXN 131072          // >= N (100000), padded

__device__ int   g_deg[2 * MAXN];    // zero-initialized at module load
__device__ float g_rdeg[2 * MAXN];

__global__ void hist_rel(const int4* __restrict__ dst, int base, int nvec)
{
    int stride = gridDim.x * blockDim.x;
    for (int v = blockIdx.x * blockDim.x + threadIdx.x; v < nvec; v += stride) {
        int4 x = __ldg(&dst[v]);
        atomicAdd(&g_deg[base + x.x], 1);
        atomicAdd(&g_deg[base + x.y], 1);
        atomicAdd(&g_deg[base + x.z], 1);
        atomicAdd(&g_deg[base + x.w], 1);
    }
}

__global__ void recip_rel(int base4)     // base4 = base/4 (int4 index)
{
    int i4 = base4 + blockIdx.x * blockDim.x + threadIdx.x;
    int4* dp = reinterpret_cast<int4*>(g_deg) + i4;
    int4 d = *dp;
    float4 r;
    // exact div.rn matches reference; deg==0 -> inf, never read back
    r.x = 1.0f / (float)d.x;
    r.y = 1.0f / (float)d.y;
    r.z = 1.0f / (float)d.z;
    r.w = 1.0f / (float)d.w;
    reinterpret_cast<float4*>(g_rdeg)[i4] = r;
    *dp = make_int4(0, 0, 0, 0);   // restore invariant for the next replay
}

__global__ void alpha_rel(const int4* __restrict__ dst,
                          float4* __restrict__ out4,
                          int base, int obase, int nvec)
{
    int stride = gridDim.x * blockDim.x;
    for (int v = blockIdx.x * blockDim.x + threadIdx.x; v < nvec; v += stride) {
        int4 x = __ldg(&dst[v]);
        float4 r;
        r.x = g_rdeg[base + x.x];
        r.y = g_rdeg[base + x.y];
        r.z = g_rdeg[base + x.z];
        r.w = g_rdeg[base + x.w];
        __stcg(&out4[obase + v], r);
    }
}

// ragged tail (E % 4 != 0): never fires for E = 1e6, kept for generality
__global__ void tail_full_kernel(const int* __restrict__ dst_ui,
                                 const int* __restrict__ dst_iu,
                                 float* __restrict__ out,
                                 int start, int E)
{
    int i = start + blockIdx.x * blockDim.x + threadIdx.x;
    if (i < E) {
        out[i]     = g_rdeg[dst_ui[i]];
        out[E + i] = g_rdeg[MAXN + dst_iu[i]];
    }
}

static cudaStream_t g_sB    = nullptr;   // host-side objects, created once;
static cudaEvent_t  g_evFork = nullptr;  // captured WORK is identical and
static cudaEvent_t  g_evJoin = nullptr;  // deterministic on every call.

extern "C" void kernel_launch(void* const* d_in, const int* in_sizes, int n_in,
                              void* d_out, int out_size)
{
    const int* dst_ui = (const int*)d_in[12];
    const int* dst_iu = (const int*)d_in[14];
    float* out = (float*)d_out;

    const int E = in_sizes[12];       // 1,000,000
    const int nvec = E / 4;
    const int TB = 256;
    // Half a wave each: two concurrent chains tile 148 SMs at 64 warps/SM.
    const int GRID = 148 * 4;
    const int RGRID = (MAXN / 4) / TB;   // 131072/4/256 = 128 CTAs

    if (!g_sB) {
        cudaStreamCreateWithFlags(&g_sB, cudaStreamNonBlocking);
        cudaEventCreateWithFlags(&g_evFork, cudaEventDisableTiming);
        cudaEventCreateWithFlags(&g_evJoin, cudaEventDisableTiming);
    }

    // ---- fork: stream B joins the capture ----
    cudaEventRecord(g_evFork, 0);
    cudaStreamWaitEvent(g_sB, g_evFork, 0);

    // chain A (origin stream): relation ui
    hist_rel<<<GRID, TB>>>((const int4*)dst_ui, 0, nvec);
    recip_rel<<<RGRID, TB>>>(0);
    alpha_rel<<<GRID, TB>>>((const int4*)dst_ui, (float4*)out, 0, 0, nvec);

    // chain B (forked stream): relation iu
    hist_rel<<<GRID, TB, 0, g_sB>>>((const int4*)dst_iu, MAXN, nvec);
    recip_rel<<<RGRID, TB, 0, g_sB>>>(MAXN / 4);
    alpha_rel<<<GRID, TB, 0, g_sB>>>((const int4*)dst_iu, (float4*)out,
                                     MAXN, nvec, nvec);

    // ---- join back onto the origin stream ----
    cudaEventRecord(g_evJoin, g_sB);
    cudaStreamWaitEvent(0, g_evJoin, 0);

    if (E % 4 != 0) {
        int start = (E / 4) * 4;
        int rem = E - start;
        tail_full_kernel<<<(rem + TB - 1) / TB, TB>>>(dst_ui, dst_iu, out, start, E);
    }
}